// round 14
// baseline (speedup 1.0000x reference)
#include <cuda_runtime.h>

#define HH 480
#define WW 640
#define NC 3
#define SKIP 5
#define PH 96            // HH/SKIP
#define PW 128           // WW/SKIP
#define NP (PH*PW)       // 12288 sampled pixels
#define BH 60            // bin rows   (GRID=8, start 4)
#define BWID 80          // bin cols
#define NB (BH*BWID)     // 4800 bins
#define BPTY 6           // bin-rows per thread (column-major ownership)
#define NRG (BH/BPTY)    // 10 row-groups
#define NTH (BWID*NRG)   // 800 worker threads (bin side)
#define BGRID 4          // 4*256 = 1024 >= 800
#define PSPLIT 148       // pixel-slice CTAs -> 4*148 = 592 CTAs (= occ-4 residency)

#define GDC_WAIT()    asm volatile("griddepcontrol.wait;" ::: "memory")
#define GDC_LAUNCH()  asm volatile("griddepcontrol.launch_dependents;" ::: "memory")

// ---------- device scratch (zero-initialized at module load) ----------
__device__ float4 g_pix[2*NP]; // {px, py, 2ux, 2uy}
__device__ float  g_dd[2*NP];  // dist
__device__ int    g_n[2];      // compacted counts (class 1,2)  -- reset by finish_k
__device__ int    g_cnt[NC];   // raw label counts (incl. cls0) -- reset by finish_k
__device__ float  g_dsum[2*NB];
__device__ float  g_rois_scratch[NC*6];
__device__ float  g_hough_scratch[NC*NB];

// ---------- kernel 1: zero hough/dsum + gather/compact/prune (R12 verbatim) ----------
#define PREP_TH (NC*NB)   // 14400 >= NP
__global__ void prep_k(const int* __restrict__ label,
                       const float* __restrict__ vert,
                       float* __restrict__ hough) {
    int i = blockIdx.x * blockDim.x + threadIdx.x;
    if (i < NC*NB) hough[i] = 0.0f;
    if (i < 2*NB)  g_dsum[i] = 0.0f;

    if (i < NP) {   // NP % 256 == 0: warps in here are fully active
        int lane = threadIdx.x & 31;
        unsigned lmlt = (1u << lane) - 1u;

        int r = i / PW, c = i % PW;
        int vy = r * SKIP, vx = c * SKIP;
        int vl = label[vy * WW + vx];

        #pragma unroll
        for (int cl = 0; cl < NC; cl++) {
            unsigned m = __ballot_sync(0xffffffffu, vl == cl);
            if (m && lane == (__ffs(m) - 1))
                atomicAdd(&g_cnt[cl], __popc(m));
        }

        float ux = 0.f, uy = 0.f, dd = 0.f;
        bool want = false;
        if (vl > 0) {
            int base = (vl * 3) * (HH * WW) + vy * WW + vx;
            ux = vert[base];
            uy = vert[base + HH * WW];
            dd = vert[base + 2 * HH * WW];
            // prune: cos <= |u|; if ux^2+uy^2 <= 0.25, cos>0.5 impossible
            want = fmaf(ux, ux, uy * uy) > 0.25f;
        }

        #pragma unroll
        for (int seg = 0; seg < 2; seg++) {
            bool p = want && (vl == seg + 1);
            unsigned m = __ballot_sync(0xffffffffu, p);
            if (m) {
                int leader = __ffs(m) - 1;
                int base = 0;
                if (lane == leader) base = atomicAdd(&g_n[seg], __popc(m));
                base = __shfl_sync(0xffffffffu, base, leader);
                if (p) {
                    int slot = seg * NP + base + __popc(m & lmlt);
                    g_pix[slot] = make_float4((float)vx, (float)vy, 2.0f * ux, 2.0f * uy);
                    g_dd[slot]  = dd;
                }
            }
        }
    }

    GDC_LAUNCH();
}

// ---------- kernel 2: voting with warp-tile conservative rejection ----------
__global__ void __launch_bounds__(256, 4)
vote_k(float* __restrict__ hough) {
    __shared__ float4 s_pix[256];
    __shared__ float  s_dd[256];

    int tid = threadIdx.x;
    int gt  = blockIdx.x * 256 + tid;          // 0..1023
    bool wactive = (gt & ~31) < NTH;           // warp-uniform (NTH=800, warp-aligned)
    bool tactive = gt < NTH;

    // thread's bins: column x = gt%80, rows rg*6 .. rg*6+5
    int bx = gt % BWID;
    int rg = gt / BWID;                        // 0..9 (garbage for inactive; unused)
    float xf  = 4.0f + 8.0f * (float)bx;
    float y0f = 4.0f + 48.0f * (float)rg;

    // warp tile bounds (uniform across the warp)
    int wb = gt & ~31;
    int xlo = wb % BWID, xhi = (wb + 31) % BWID;
    int rglo = wb / BWID, rghi = (wb + 31) / BWID;
    if (xhi < xlo) { xlo = 0; xhi = BWID - 1; }   // wrap warp: conservative full width
    float Xlo = 4.0f + 8.0f * (float)xlo;
    float Xhi = 4.0f + 8.0f * (float)xhi;
    float Ylo = 4.0f + 48.0f * (float)rglo;
    float Yhi = 4.0f + 48.0f * (float)rghi + 40.0f;

    GDC_WAIT();   // prep_k's writes visible

    for (int seg = 0; seg < 2; seg++) {
        int n     = g_n[seg];
        int chunk = (n + PSPLIT - 1) / PSPLIT;
        int start = blockIdx.y * chunk;
        int end   = min(start + chunk, n);

        float aH[BPTY], aD[BPTY];
        #pragma unroll
        for (int r = 0; r < BPTY; r++) { aH[r] = 0.f; aD[r] = 0.f; }

        for (int t = start; t < end; t += 256) {
            int m = min(256, end - t);
            __syncthreads();
            if (tid < m) {
                int s = seg * NP + t + tid;
                s_pix[tid] = g_pix[s];
                s_dd[tid]  = g_dd[s];
            }
            __syncthreads();

            if (wactive) {
                for (int j = 0; j < m; j++) {
                    float4 P = s_pix[j];             // LDS.128 broadcast
                    float px = P.x, py = P.y, ux2 = P.z, uy2 = P.w;

                    // ---- conservative warp-tile test (identical in all lanes) ----
                    float dxl = Xlo - px, dxh = Xhi - px;
                    float dyl = Ylo - py, dyh = Yhi - py;
                    float dotmax = fmaxf(dxl * ux2, dxh * ux2)
                                 + fmaxf(dyl * uy2, dyh * uy2);
                    float minxx = (dxl <= 0.0f && dxh >= 0.0f)
                                ? 0.0f : fminf(dxl * dxl, dxh * dxh);
                    float minyy = (dyl <= 0.0f && dyh >= 0.0f)
                                ? 0.0f : fminf(dyl * dyl, dyh * dyh);
                    float nmin = minxx + minyy;
                    // any passing bin has dot > 1e-3 and dot^2 > nxy >= nmin;
                    // 0.999 margin >> fp32 rounding -> rejection is safe
                    if (!(dotmax > 0.0f && dotmax * dotmax > nmin * 0.999f))
                        continue;                    // warp-uniform skip

                    // ---- exact per-bin evaluation (column of 6 rows) ----
                    float dd  = s_dd[j];
                    float ddx = xf - px;
                    float dxu = ddx * ux2;
                    float xx  = fmaf(ddx, ddx, 1e-6f);
                    #pragma unroll
                    for (int r = 0; r < BPTY; r++) {
                        float ddy = (y0f + 8.0f * (float)r) - py;
                        float nxy = fmaf(ddy, ddy, xx);
                        float dot = fmaf(ddy, uy2, dxu);
                        bool  ok  = (dot > 0.0f) && (dot * dot > nxy);
                        aH[r] += ok ? 1.0f : 0.0f;
                        aD[r] += ok ? dd   : 0.0f;
                    }
                }
            }
        }

        if (tactive) {
            #pragma unroll
            for (int r = 0; r < BPTY; r++) {
                if (aH[r] != 0.0f) {
                    int bin = (rg * BPTY + r) * BWID + bx;
                    atomicAdd(&hough[(seg + 1) * NB + bin], aH[r]);
                    atomicAdd(&g_dsum[seg * NB + bin], aD[r]);
                }
            }
        }
        __syncthreads();
    }

    GDC_LAUNCH();
}

// ---------- kernel 3: argmax + ROI epilogue (3 CTAs, PDL) + counter reset ----------
__global__ void finish_k(const float* __restrict__ hough,
                         float* __restrict__ rois,
                         const float* __restrict__ meta,
                         const float* __restrict__ extents) {
    __shared__ float sv[256];
    __shared__ int   si[256];
    int c   = blockIdx.x;
    int tid = threadIdx.x;

    GDC_WAIT();

    if (c > 0) {
        float best = -1.0f; int bi = 0;
        #pragma unroll
        for (int k = 0; k < 19; k++) {
            int i = tid + k * 256;
            float v = (i < NB) ? hough[c * NB + i] : -2.0f;
            if (v > best) { best = v; bi = i; }   // ascending i -> first max kept
        }
        sv[tid] = best; si[tid] = bi;
        __syncthreads();
        #pragma unroll
        for (int s = 128; s > 0; s >>= 1) {
            if (tid < s) {
                float v2 = sv[tid + s]; int i2 = si[tid + s];
                if (v2 > sv[tid] || (v2 == sv[tid] && i2 < si[tid])) {
                    sv[tid] = v2; si[tid] = i2;
                }
            }
            __syncthreads();
        }
    }

    if (tid == 0) {
        int peak; float votes;
        if (c == 0) { peak = 0; votes = 0.0f; }   // class-0 hough row is identically 0
        else        { peak = si[0]; votes = sv[0]; }
        float ds    = (c > 0) ? g_dsum[(c - 1) * NB + peak] : 0.0f;
        float depth = ds / fmaxf(votes, 1.0f);
        float cx = 4.0f + 8.0f * (float)(peak % BWID);
        float cy = 4.0f + 8.0f * (float)(peak / BWID);
        float cnt = (float)g_cnt[c];
        float score = votes / fmaxf(cnt, 1.0f);
        bool  valid = (cnt > 5.0f) && (score > 0.3f);
        float fx = meta[0], fy = meta[4];
        float e0 = extents[c*3+0], e1 = extents[c*3+1], e2 = extents[c*3+2];
        float diag = sqrtf(e0*e0 + e1*e1 + e2*e2);
        float sz = fmaxf(fabsf(depth), 0.001f);
        float bw = fabsf(diag * fx) / sz;
        float bh = fabsf(diag * fy) / sz;
        rois[c*6+0] = (float)c;
        rois[c*6+1] = cx - bw * 0.5f;
        rois[c*6+2] = cy - bh * 0.5f;
        rois[c*6+3] = cx + bw * 0.5f;
        rois[c*6+4] = cy + bh * 0.5f;
        rois[c*6+5] = valid ? score : 0.0f;

        // reset counters for the next graph replay
        g_cnt[c] = 0;
        if (c == 0) { g_n[0] = 0; g_n[1] = 0; }
    }
}

extern "C" void kernel_launch(void* const* d_in, const int* in_sizes, int n_in,
                              void* d_out, int out_size) {
    const int*   label = (const int*)  d_in[0];
    const float* vert  = (const float*)d_in[1];
    const float* meta  = (const float*)d_in[2];
    const float* ext   = (const float*)d_in[3];
    float* out = (float*)d_out;

    // Output is the flattened tuple (rois[3,6], hough[3,4800]) -> 18 + 14400.
    float *rois_p, *hough_p;
    if (out_size >= NC*6 + NC*NB) {
        rois_p = out; hough_p = out + NC*6;
    } else if (out_size >= NC*NB) {
        void* tmp = nullptr;
        cudaGetSymbolAddress(&tmp, g_rois_scratch);
        rois_p = (float*)tmp; hough_p = out;
    } else {
        void* tmp = nullptr;
        cudaGetSymbolAddress(&tmp, g_hough_scratch);
        rois_p = out; hough_p = (float*)tmp;
    }

    prep_k<<<(PREP_TH + 255) / 256, 256>>>(label, vert, hough_p);

    cudaLaunchAttribute pdl[1];
    pdl[0].id = cudaLaunchAttributeProgrammaticStreamSerialization;
    pdl[0].val.programmaticStreamSerializationAllowed = 1;

    {   // vote_k with PDL
        cudaLaunchConfig_t cfg = {};
        cfg.gridDim  = dim3(BGRID, PSPLIT);
        cfg.blockDim = dim3(256);
        cfg.attrs    = pdl;
        cfg.numAttrs = 1;
        cudaLaunchKernelEx(&cfg, vote_k, hough_p);
    }
    {   // finish_k with PDL
        cudaLaunchConfig_t cfg = {};
        cfg.gridDim  = dim3(NC);
        cfg.blockDim = dim3(256);
        cfg.attrs    = pdl;
        cfg.numAttrs = 1;
        cudaLaunchKernelEx(&cfg, finish_k, (const float*)hough_p, rois_p, meta, ext);
    }
}